// round 8
// baseline (speedup 1.0000x reference)
#include <cuda_runtime.h>

#define BB 4
#define DD 8
#define HH 512
#define WW 640
#define NB 16
#define HW (HH*WW)

// Quad image: per pixel (v00, v01, v10, v11) with border clamp baked in. 20.97 MB (L2-resident).
__device__ float4 g_quad[BB*HW];

__global__ void __launch_bounds__(256) prep_kernel(const float* __restrict__ ds) {
    int t = blockIdx.x * 256 + threadIdx.x;
    if (t >= BB*HW) return;
    int b = t / HW;
    int p = t - b*HW;
    int y = p / WW;
    int x = p - y*WW;
    const float* c = ds + (b*DD + DD/2)*HW;   // center plane (channel 4)
    int xp = (x + 1 < WW) ? x + 1 : WW - 1;
    int yp = (y + 1 < HH) ? y + 1 : HH - 1;
    float v00 = __ldg(c + y*WW + x);
    float v01 = __ldg(c + y*WW + xp);
    float v10 = __ldg(c + yp*WW + x);
    float v11 = __ldg(c + yp*WW + xp);
    g_quad[t] = make_float4(v00, v01, v10, v11);
}

// compare-exchange
#define CE(i,j) { float _lo = fminf(v[i], v[j]); v[j] = fmaxf(v[i], v[j]); v[i] = _lo; }

__global__ void __launch_bounds__(256, 2) main_kernel(const float* __restrict__ ds,
                                                      const float* __restrict__ grid,
                                                      float* __restrict__ out) {
    int t = blockIdx.x * 256 + threadIdx.x;   // exactly BB*HW threads, 1 px each
    int b = t / HW;
    int p = t - b*HW;

    const float2* g2 = (const float2*)grid + (size_t)b*NB*HW + p;
    const float4* q  = g_quad + b*HW;

    // ---- Phase A: batch all 16 grid coordinate loads (coalesced, streaming) ----
    float2 g[NB];
    #pragma unroll
    for (int n = 0; n < NB; ++n) g[n] = __ldcs(g2 + n*HW);

    // ---- Phase B: compute all weights, issue all 16 scattered quad gathers ----
    float4 c[NB];
    float  wx[NB], wy[NB];
    #pragma unroll
    for (int n = 0; n < NB; ++n) {
        float fx = fminf(fmaxf(fmaf(g[n].x, (float)(WW/2), (WW-1)*0.5f), 0.0f), (float)(WW-1));
        float fy = fminf(fmaxf(fmaf(g[n].y, (float)(HH/2), (HH-1)*0.5f), 0.0f), (float)(HH-1));
        int xi = (int)fx;                  // fx >= 0 -> trunc == floor
        int yi = (int)fy;
        wx[n] = fx - (float)xi;
        wy[n] = fy - (float)yi;
        c[n] = q[yi*WW + xi];              // single aligned 16B gather (L2 hit)
    }

    // ---- Phase C: consume gathers ----
    float v[24];
    #pragma unroll
    for (int n = 0; n < NB; ++n) {
        float top = fmaf(wx[n], c[n].y - c[n].x, c[n].x);
        float bot = fmaf(wx[n], c[n].w - c[n].z, c[n].z);
        v[8 + n] = fmaf(wy[n], bot - top, top);
    }

    // ---- Phase D: 8 depth planes (after gathers: keeps gather-window live set small) ----
    const float* dsp = ds + b*DD*HW + p;
    #pragma unroll
    for (int d = 0; d < DD; ++d) v[d] = __ldcs(dsp + d*HW);

    // ---- Batcher merge-exchange sorting network, n=24 (127 comparators) ----
    // p=16
    CE(0,16) CE(1,17) CE(2,18) CE(3,19) CE(4,20) CE(5,21) CE(6,22) CE(7,23)
    // p=8
    CE(0,8) CE(1,9) CE(2,10) CE(3,11) CE(4,12) CE(5,13) CE(6,14) CE(7,15)
    CE(8,16) CE(9,17) CE(10,18) CE(11,19) CE(12,20) CE(13,21) CE(14,22) CE(15,23)
    // p=4
    CE(0,4) CE(1,5) CE(2,6) CE(3,7) CE(8,12) CE(9,13) CE(10,14) CE(11,15)
    CE(16,20) CE(17,21) CE(18,22) CE(19,23)
    CE(4,16) CE(5,17) CE(6,18) CE(7,19)
    CE(4,8) CE(5,9) CE(6,10) CE(7,11) CE(12,16) CE(13,17) CE(14,18) CE(15,19)
    // p=2
    CE(0,2) CE(1,3) CE(4,6) CE(5,7) CE(8,10) CE(9,11) CE(12,14) CE(13,15)
    CE(16,18) CE(17,19) CE(20,22) CE(21,23)
    CE(2,16) CE(3,17) CE(6,20) CE(7,21)
    CE(2,8) CE(3,9) CE(6,12) CE(7,13) CE(10,16) CE(11,17) CE(14,20) CE(15,21)
    CE(2,4) CE(3,5) CE(6,8) CE(7,9) CE(10,12) CE(11,13) CE(14,16) CE(15,17)
    CE(18,20) CE(19,21)
    // p=1
    CE(0,1) CE(2,3) CE(4,5) CE(6,7) CE(8,9) CE(10,11) CE(12,13) CE(14,15)
    CE(16,17) CE(18,19) CE(20,21) CE(22,23)
    CE(1,16) CE(3,18) CE(5,20) CE(7,22)
    CE(1,8) CE(3,10) CE(5,12) CE(7,14) CE(9,16) CE(11,18) CE(13,20) CE(15,22)
    CE(1,4) CE(3,6) CE(5,8) CE(7,10) CE(9,12) CE(11,14) CE(13,16) CE(15,18)
    CE(17,20) CE(19,22)
    CE(1,2) CE(3,4) CE(5,6) CE(7,8) CE(9,10) CE(11,12) CE(13,14) CE(15,16)
    CE(17,18) CE(19,20) CE(21,22)

    // 24 coalesced streaming stores
    float* o = out + b*24*HW + p;
    #pragma unroll
    for (int k = 0; k < 24; ++k) __stcs(o + k*HW, v[k]);
}

extern "C" void kernel_launch(void* const* d_in, const int* in_sizes, int n_in,
                              void* d_out, int out_size) {
    // Identify tensors by element count:
    // depth_sample: 4*8*512*640 = 10485760, grid: 4*16*512*640*2 = 41943040
    const float* ds = nullptr;
    const float* grid = nullptr;
    for (int i = 0; i < n_in; ++i) {
        if (in_sizes[i] == BB*DD*HW)        ds   = (const float*)d_in[i];
        else if (in_sizes[i] == BB*NB*HW*2) grid = (const float*)d_in[i];
    }
    float* out = (float*)d_out;

    prep_kernel<<<(BB*HW)/256, 256>>>(ds);
    main_kernel<<<(BB*HW)/256, 256>>>(ds, grid, out);
}

// round 9
// speedup vs baseline: 1.0838x; 1.0838x over previous
#include <cuda_runtime.h>

#define BB 4
#define DD 8
#define HH 512
#define WW 640
#define NB 16
#define HW (HH*WW)

// Quad image: per pixel (v00, v01, v10, v11) with border clamp baked in.
// 4*512*640*16B = 20.97 MB static scratch (L2-resident).
__device__ float4 g_quad[BB*HW];

__global__ void __launch_bounds__(256) prep_kernel(const float* __restrict__ ds) {
    int t = blockIdx.x * 256 + threadIdx.x;
    if (t >= BB*HW) return;
    int b = t / HW;
    int p = t - b*HW;
    int y = p / WW;
    int x = p - y*WW;
    const float* c = ds + (b*DD + DD/2)*HW;   // center plane (channel 4)
    int xp = (x + 1 < WW) ? x + 1 : WW - 1;
    int yp = (y + 1 < HH) ? y + 1 : HH - 1;
    float v00 = __ldg(c + y*WW + x);
    float v01 = __ldg(c + y*WW + xp);
    float v10 = __ldg(c + yp*WW + x);
    float v11 = __ldg(c + yp*WW + xp);
    g_quad[t] = make_float4(v00, v01, v10, v11);
}

// compare-exchange
#define CE(i,j) { float _lo = fminf(v[i], v[j]); v[j] = fmaxf(v[i], v[j]); v[i] = _lo; }

__global__ void __launch_bounds__(256) main_kernel(const float* __restrict__ ds,
                                                   const float* __restrict__ grid,
                                                   float* __restrict__ out) {
    int t = blockIdx.x * 256 + threadIdx.x;   // exactly BB*HW threads
    int b = t / HW;
    int p = t - b*HW;                          // p = y*WW + x

    float v[24];

    // 8 depth planes (streaming, evict-first)
    const float* dsp = ds + b*DD*HW + p;
    #pragma unroll
    for (int d = 0; d < DD; ++d) v[d] = __ldcs(dsp + d*HW);

    // 16 bilinear samples: one float2 grid read + one float4 quad gather each.
    // Gather uses __ldcg: L1-bypass (L2-only) — random over 21MB never hits L1;
    // skipping the L1 fill/evict saves L1 data-array bandwidth.
    const float2* g2 = (const float2*)grid + (size_t)b*NB*HW + p;
    const float4* q  = g_quad + b*HW;
    #pragma unroll
    for (int n = 0; n < NB; ++n) {
        float2 g = __ldcs(g2 + n*HW);
        float fx = fminf(fmaxf(fmaf(g.x, (float)(WW/2), (WW-1)*0.5f), 0.0f), (float)(WW-1));
        float fy = fminf(fmaxf(fmaf(g.y, (float)(HH/2), (HH-1)*0.5f), 0.0f), (float)(HH-1));
        int xi = (int)fx;                      // fx >= 0 -> trunc == floor
        int yi = (int)fy;
        float wx = fx - (float)xi;
        float wy = fy - (float)yi;
        float4 c = __ldcg(q + yi*WW + xi);     // single 16B gather, L2-direct
        float top = c.x + wx*(c.y - c.x);
        float bot = c.z + wx*(c.w - c.z);
        v[8 + n] = top + wy*(bot - top);
    }

    // ---- Batcher merge-exchange sorting network, n=24 (127 comparators) ----
    // p=16
    CE(0,16) CE(1,17) CE(2,18) CE(3,19) CE(4,20) CE(5,21) CE(6,22) CE(7,23)
    // p=8
    CE(0,8) CE(1,9) CE(2,10) CE(3,11) CE(4,12) CE(5,13) CE(6,14) CE(7,15)
    CE(8,16) CE(9,17) CE(10,18) CE(11,19) CE(12,20) CE(13,21) CE(14,22) CE(15,23)
    // p=4
    CE(0,4) CE(1,5) CE(2,6) CE(3,7) CE(8,12) CE(9,13) CE(10,14) CE(11,15)
    CE(16,20) CE(17,21) CE(18,22) CE(19,23)
    CE(4,16) CE(5,17) CE(6,18) CE(7,19)
    CE(4,8) CE(5,9) CE(6,10) CE(7,11) CE(12,16) CE(13,17) CE(14,18) CE(15,19)
    // p=2
    CE(0,2) CE(1,3) CE(4,6) CE(5,7) CE(8,10) CE(9,11) CE(12,14) CE(13,15)
    CE(16,18) CE(17,19) CE(20,22) CE(21,23)
    CE(2,16) CE(3,17) CE(6,20) CE(7,21)
    CE(2,8) CE(3,9) CE(6,12) CE(7,13) CE(10,16) CE(11,17) CE(14,20) CE(15,21)
    CE(2,4) CE(3,5) CE(6,8) CE(7,9) CE(10,12) CE(11,13) CE(14,16) CE(15,17)
    CE(18,20) CE(19,21)
    // p=1
    CE(0,1) CE(2,3) CE(4,5) CE(6,7) CE(8,9) CE(10,11) CE(12,13) CE(14,15)
    CE(16,17) CE(18,19) CE(20,21) CE(22,23)
    CE(1,16) CE(3,18) CE(5,20) CE(7,22)
    CE(1,8) CE(3,10) CE(5,12) CE(7,14) CE(9,16) CE(11,18) CE(13,20) CE(15,22)
    CE(1,4) CE(3,6) CE(5,8) CE(7,10) CE(9,12) CE(11,14) CE(13,16) CE(15,18)
    CE(17,20) CE(19,22)
    CE(1,2) CE(3,4) CE(5,6) CE(7,8) CE(9,10) CE(11,12) CE(13,14) CE(15,16)
    CE(17,18) CE(19,20) CE(21,22)

    // 24 coalesced streaming stores
    float* o = out + b*24*HW + p;
    #pragma unroll
    for (int k = 0; k < 24; ++k) __stcs(o + k*HW, v[k]);
}

extern "C" void kernel_launch(void* const* d_in, const int* in_sizes, int n_in,
                              void* d_out, int out_size) {
    // Identify tensors by element count:
    // depth_sample: 4*8*512*640 = 10485760, grid: 4*16*512*640*2 = 41943040
    const float* ds = nullptr;
    const float* grid = nullptr;
    for (int i = 0; i < n_in; ++i) {
        if (in_sizes[i] == BB*DD*HW)        ds   = (const float*)d_in[i];
        else if (in_sizes[i] == BB*NB*HW*2) grid = (const float*)d_in[i];
    }
    float* out = (float*)d_out;

    prep_kernel<<<(BB*HW)/256, 256>>>(ds);
    main_kernel<<<(BB*HW)/256, 256>>>(ds, grid, out);
}

// round 10
// speedup vs baseline: 1.1033x; 1.0180x over previous
#include <cuda_runtime.h>

#define BB 4
#define DD 8
#define HH 512
#define WW 640
#define NB 16
#define HW (HH*WW)

// Quad image: per pixel (v00, v01, v10, v11) with border clamp baked in.
// 4*512*640*16B = 20.97 MB static scratch (L2-resident).
__device__ float4 g_quad[BB*HW];

__global__ void __launch_bounds__(256) prep_kernel(const float* __restrict__ ds) {
    // Allow the dependent main_kernel to begin launching immediately; it will
    // gridDependencySynchronize() before touching g_quad.
    cudaTriggerProgrammaticLaunchCompletion();

    int t = blockIdx.x * 256 + threadIdx.x;
    if (t >= BB*HW) return;
    int b = t / HW;
    int p = t - b*HW;
    int y = p / WW;
    int x = p - y*WW;
    const float* c = ds + (b*DD + DD/2)*HW;   // center plane (channel 4)
    int xp = (x + 1 < WW) ? x + 1 : WW - 1;
    int yp = (y + 1 < HH) ? y + 1 : HH - 1;
    float v00 = __ldg(c + y*WW + x);
    float v01 = __ldg(c + y*WW + xp);
    float v10 = __ldg(c + yp*WW + x);
    float v11 = __ldg(c + yp*WW + xp);
    g_quad[t] = make_float4(v00, v01, v10, v11);
}

// compare-exchange
#define CE(i,j) { float _lo = fminf(v[i], v[j]); v[j] = fmaxf(v[i], v[j]); v[i] = _lo; }

__global__ void __launch_bounds__(256) main_kernel(const float* __restrict__ ds,
                                                   const float* __restrict__ grid,
                                                   float* __restrict__ out) {
    int t = blockIdx.x * 256 + threadIdx.x;   // exactly BB*HW threads
    int b = t / HW;
    int p = t - b*HW;                          // p = y*WW + x

    float v[24];

    // 8 depth planes (streaming, evict-first) — independent of g_quad,
    // overlaps with prep_kernel's tail under PDL.
    const float* dsp = ds + b*DD*HW + p;
    #pragma unroll
    for (int d = 0; d < DD; ++d) v[d] = __ldcs(dsp + d*HW);

    // Wait for prep_kernel to complete before reading g_quad.
    cudaGridDependencySynchronize();

    // 16 bilinear samples: one float2 grid read + one float4 quad gather each.
    const float2* g2 = (const float2*)grid + (size_t)b*NB*HW + p;
    const float4* q  = g_quad + b*HW;
    #pragma unroll
    for (int n = 0; n < NB; ++n) {
        float2 g = __ldcs(g2 + n*HW);
        float fx = fminf(fmaxf(fmaf(g.x, (float)(WW/2), (WW-1)*0.5f), 0.0f), (float)(WW-1));
        float fy = fminf(fmaxf(fmaf(g.y, (float)(HH/2), (HH-1)*0.5f), 0.0f), (float)(HH-1));
        int xi = (int)fx;                      // fx >= 0 -> trunc == floor
        int yi = (int)fy;
        float wx = fx - (float)xi;
        float wy = fy - (float)yi;
        float4 c = __ldcg(q + yi*WW + xi);     // single 16B gather, L2-direct
        float top = c.x + wx*(c.y - c.x);
        float bot = c.z + wx*(c.w - c.z);
        v[8 + n] = top + wy*(bot - top);
    }

    // ---- Batcher merge-exchange sorting network, n=24 (127 comparators) ----
    // p=16
    CE(0,16) CE(1,17) CE(2,18) CE(3,19) CE(4,20) CE(5,21) CE(6,22) CE(7,23)
    // p=8
    CE(0,8) CE(1,9) CE(2,10) CE(3,11) CE(4,12) CE(5,13) CE(6,14) CE(7,15)
    CE(8,16) CE(9,17) CE(10,18) CE(11,19) CE(12,20) CE(13,21) CE(14,22) CE(15,23)
    // p=4
    CE(0,4) CE(1,5) CE(2,6) CE(3,7) CE(8,12) CE(9,13) CE(10,14) CE(11,15)
    CE(16,20) CE(17,21) CE(18,22) CE(19,23)
    CE(4,16) CE(5,17) CE(6,18) CE(7,19)
    CE(4,8) CE(5,9) CE(6,10) CE(7,11) CE(12,16) CE(13,17) CE(14,18) CE(15,19)
    // p=2
    CE(0,2) CE(1,3) CE(4,6) CE(5,7) CE(8,10) CE(9,11) CE(12,14) CE(13,15)
    CE(16,18) CE(17,19) CE(20,22) CE(21,23)
    CE(2,16) CE(3,17) CE(6,20) CE(7,21)
    CE(2,8) CE(3,9) CE(6,12) CE(7,13) CE(10,16) CE(11,17) CE(14,20) CE(15,21)
    CE(2,4) CE(3,5) CE(6,8) CE(7,9) CE(10,12) CE(11,13) CE(14,16) CE(15,17)
    CE(18,20) CE(19,21)
    // p=1
    CE(0,1) CE(2,3) CE(4,5) CE(6,7) CE(8,9) CE(10,11) CE(12,13) CE(14,15)
    CE(16,17) CE(18,19) CE(20,21) CE(22,23)
    CE(1,16) CE(3,18) CE(5,20) CE(7,22)
    CE(1,8) CE(3,10) CE(5,12) CE(7,14) CE(9,16) CE(11,18) CE(13,20) CE(15,22)
    CE(1,4) CE(3,6) CE(5,8) CE(7,10) CE(9,12) CE(11,14) CE(13,16) CE(15,18)
    CE(17,20) CE(19,22)
    CE(1,2) CE(3,4) CE(5,6) CE(7,8) CE(9,10) CE(11,12) CE(13,14) CE(15,16)
    CE(17,18) CE(19,20) CE(21,22)

    // 24 coalesced streaming stores
    float* o = out + b*24*HW + p;
    #pragma unroll
    for (int k = 0; k < 24; ++k) __stcs(o + k*HW, v[k]);
}

extern "C" void kernel_launch(void* const* d_in, const int* in_sizes, int n_in,
                              void* d_out, int out_size) {
    // Identify tensors by element count:
    // depth_sample: 4*8*512*640 = 10485760, grid: 4*16*512*640*2 = 41943040
    const float* ds = nullptr;
    const float* grid = nullptr;
    for (int i = 0; i < n_in; ++i) {
        if (in_sizes[i] == BB*DD*HW)        ds   = (const float*)d_in[i];
        else if (in_sizes[i] == BB*NB*HW*2) grid = (const float*)d_in[i];
    }
    float* out = (float*)d_out;

    const int nblk = (BB*HW)/256;   // 5120

    // Primary: prep (triggers programmatic completion at its start).
    prep_kernel<<<nblk, 256>>>(ds);

    // Secondary: main, launched with Programmatic Stream Serialization so its
    // pre-gather phase overlaps prep's execution.
    cudaLaunchConfig_t cfg = {};
    cfg.gridDim = dim3(nblk, 1, 1);
    cfg.blockDim = dim3(256, 1, 1);
    cfg.dynamicSmemBytes = 0;
    cfg.stream = 0;
    cudaLaunchAttribute attr[1];
    attr[0].id = cudaLaunchAttributeProgrammaticStreamSerialization;
    attr[0].val.programmaticStreamSerializationAllowed = 1;
    cfg.attrs = attr;
    cfg.numAttrs = 1;
    cudaLaunchKernelEx(&cfg, main_kernel, ds, grid, out);
}